// round 1
// baseline (speedup 1.0000x reference)
#include <cuda_runtime.h>

#define NI   256
#define QK   32
#define BS   4
#define NPIX 4096
#define BM   64
#define BN   64

// Scratch (device globals: allocation-free contract)
__device__ float g_Q[BS * NPIX * QK];   //  2 MB  [b][n][32]
__device__ float g_K[BS * NPIX * QK];   //  2 MB  [b][n][32]
__device__ float g_V[BS * NPIX * NI];   // 16 MB  [b][n][256]

// ---------------------------------------------------------------------------
// Projection: dst[b][n][o] = sum_c W[o][c] * x[b][c][n] + bias[o]
// Tile: 32 o  x 128 n, K-chunks of 32. 256 threads = 8(oy) x 32(nx),
// each thread 4x4 register tile.
// ---------------------------------------------------------------------------
__global__ __launch_bounds__(256) void proj_kernel(
    const float* __restrict__ x, const float* __restrict__ W,
    const float* __restrict__ bias, int which)
{
    float* dst; int ldo;
    if (which == 0)      { dst = g_Q; ldo = QK; }
    else if (which == 1) { dst = g_K; ldo = QK; }
    else                 { dst = g_V; ldo = NI; }

    __shared__ float sX[4352];      // [32][128] compute tile, then [128][33] transpose
    __shared__ float sW[32 * 33];

    const int t  = threadIdx.x;
    const int nx = t & 31;
    const int oy = t >> 5;          // 0..7
    const int b  = blockIdx.z;
    const int n0 = blockIdx.x * 128;
    const int o0 = blockIdx.y * 32;

    float acc[4][4];
    #pragma unroll
    for (int i = 0; i < 4; i++)
        #pragma unroll
        for (int j = 0; j < 4; j++) acc[i][j] = 0.f;

    for (int k0 = 0; k0 < NI; k0 += 32) {
        // x chunk [32 k][128 n], float4 coalesced
        const float4* xp = reinterpret_cast<const float4*>(
            x + ((size_t)(b * NI + k0)) * NPIX + n0);
        #pragma unroll
        for (int r = 0; r < 4; r++) {
            int fi = t + r * 256;
            int kk = fi >> 5, c4 = fi & 31;
            reinterpret_cast<float4*>(sX)[kk * 32 + c4] = xp[(size_t)kk * 1024 + c4];
        }
        // W chunk [32 o][32 k], padded rows (33)
        #pragma unroll
        for (int r = 0; r < 4; r++) {
            int ei = t + r * 256;
            int o = ei >> 5, kk = ei & 31;
            sW[o * 33 + kk] = W[(size_t)(o0 + o) * NI + k0 + kk];
        }
        __syncthreads();

        #pragma unroll
        for (int kk = 0; kk < 32; kk++) {
            float wf[4], xf[4];
            #pragma unroll
            for (int i = 0; i < 4; i++) wf[i] = sW[(oy + 8 * i) * 33 + kk]; // broadcast
            #pragma unroll
            for (int j = 0; j < 4; j++) xf[j] = sX[kk * 128 + nx + 32 * j]; // stride-1
            #pragma unroll
            for (int i = 0; i < 4; i++)
                #pragma unroll
                for (int j = 0; j < 4; j++)
                    acc[i][j] = fmaf(wf[i], xf[j], acc[i][j]);
        }
        __syncthreads();
    }

    // bias + transpose into sX as [128 n][33]
    #pragma unroll
    for (int i = 0; i < 4; i++) {
        float bb = bias[o0 + oy + 8 * i];
        #pragma unroll
        for (int j = 0; j < 4; j++)
            sX[(nx + 32 * j) * 33 + oy + 8 * i] = acc[i][j] + bb;   // stride-33: conflict-free
    }
    __syncthreads();

    // coalesced store: rows of 32 o per pixel
    #pragma unroll
    for (int r = 0; r < 4; r++) {
        int fi = t + r * 256;
        int n = fi >> 3, o4 = (fi & 7) * 4;
        float4 v;
        v.x = sX[n * 33 + o4 + 0];
        v.y = sX[n * 33 + o4 + 1];
        v.z = sX[n * 33 + o4 + 2];
        v.w = sX[n * 33 + o4 + 3];
        reinterpret_cast<float4*>(dst + ((size_t)(b * NPIX + n0 + n)) * ldo + o0)[o4 >> 2] = v;
    }
}

// ---------------------------------------------------------------------------
// Flash attention. One CTA: 64 queries (full 256 channels). 256 threads
// = 32(tx: channel) x 8(ty: query), per-thread acc[8 q][8 c].
// Dynamic smem layout (floats):
//   sQ [64][33]      @ 0      (2112)
//   sK [64][33]      @ 2112   (2112)
//   rmax/rsum/alpha  @ 4224   (3*64)
//   sV [64][256]     @ 4416   (16384)   \ overlaid by epilogue sT [256][65]
//   sS [64][65]      @ 20800  (4160)    /
// total 24960 floats = 99840 B; 2 CTAs/SM.
// ---------------------------------------------------------------------------
#define SMEM_FLOATS 24960

__global__ __launch_bounds__(256, 2) void attn_kernel(
    const float* __restrict__ x, const float* __restrict__ gamma,
    float* __restrict__ out)
{
    extern __shared__ float sm[];
    float* sQ     = sm;
    float* sK     = sm + 2112;
    float* rmax   = sm + 4224;
    float* rsum   = sm + 4288;
    float* salpha = sm + 4352;
    float* sV     = sm + 4416;
    float* sS     = sm + 4416 + 16384;
    float* sT     = sm + 4416;          // epilogue overlay [256][65]

    const int t  = threadIdx.x;
    const int tx = t & 31;
    const int ty = t >> 5;
    const int b  = blockIdx.y;
    const int n0 = blockIdx.x * BM;

    // Load Q tile [64][32] (coalesced), pad rows to 33
    const float* Qb = g_Q + ((size_t)(b * NPIX + n0)) * QK;
    #pragma unroll
    for (int r = 0; r < 8; r++) {
        int e = t + r * 256;
        int row = e >> 5, d = e & 31;
        sQ[row * 33 + d] = Qb[e];
    }
    if (t < 64) { rmax[t] = -1e30f; rsum[t] = 0.f; }

    float acc[8][8];
    #pragma unroll
    for (int qi = 0; qi < 8; qi++)
        #pragma unroll
        for (int ci = 0; ci < 8; ci++) acc[qi][ci] = 0.f;
    __syncthreads();

    for (int jt = 0; jt < NPIX / BN; jt++) {
        const int j0 = jt * BN;

        // K tile [64][32]
        const float* Kb = g_K + ((size_t)(b * NPIX + j0)) * QK;
        #pragma unroll
        for (int r = 0; r < 8; r++) {
            int e = t + r * 256;
            int row = e >> 5, d = e & 31;
            sK[row * 33 + d] = Kb[e];
        }
        // V tile [64][256] float4
        const float4* Vb = reinterpret_cast<const float4*>(
            g_V + ((size_t)(b * NPIX + j0)) * NI);
        #pragma unroll
        for (int r = 0; r < 16; r++) {
            int fi = t + r * 256;
            int row = fi >> 6, c4 = fi & 63;
            reinterpret_cast<float4*>(sV)[row * 64 + c4] = Vb[row * 64 + c4];
        }
        __syncthreads();

        // S = Q K^T : each thread 8 queries x 2 keys (tx, tx+32)
        float s0[8], s1[8];
        #pragma unroll
        for (int qi = 0; qi < 8; qi++) { s0[qi] = 0.f; s1[qi] = 0.f; }
        #pragma unroll
        for (int d = 0; d < 32; d++) {
            float k0v = sK[tx * 33 + d];          // conflict-free (stride 33)
            float k1v = sK[(tx + 32) * 33 + d];
            #pragma unroll
            for (int qi = 0; qi < 8; qi++) {
                float qv = sQ[(ty + 8 * qi) * 33 + d];   // broadcast within warp
                s0[qi] = fmaf(qv, k0v, s0[qi]);
                s1[qi] = fmaf(qv, k1v, s1[qi]);
            }
        }
        #pragma unroll
        for (int qi = 0; qi < 8; qi++) {
            sS[(ty + 8 * qi) * 65 + tx]      = s0[qi];
            sS[(ty + 8 * qi) * 65 + tx + 32] = s1[qi];
        }
        __syncthreads();

        // Online softmax: thread t<64 owns row t (stride-65: conflict-free)
        if (t < 64) {
            float mo = rmax[t];
            float tm = -1e30f;
            #pragma unroll 8
            for (int jj = 0; jj < 64; jj++) tm = fmaxf(tm, sS[t * 65 + jj]);
            float nm = fmaxf(mo, tm);
            float a  = __expf(mo - nm);
            float s  = 0.f;
            #pragma unroll 8
            for (int jj = 0; jj < 64; jj++) {
                float p = __expf(sS[t * 65 + jj] - nm);
                sS[t * 65 + jj] = p;
                s += p;
            }
            rsum[t] = a * rsum[t] + s;
            rmax[t] = nm;
            salpha[t] = a;
        }
        __syncthreads();

        // Rescale + O += P @ V
        float al[8];
        #pragma unroll
        for (int qi = 0; qi < 8; qi++) al[qi] = salpha[ty + 8 * qi];
        #pragma unroll
        for (int qi = 0; qi < 8; qi++)
            #pragma unroll
            for (int ci = 0; ci < 8; ci++) acc[qi][ci] *= al[qi];

        #pragma unroll 4
        for (int j = 0; j < 64; j++) {
            float pv[8], vv[8];
            #pragma unroll
            for (int qi = 0; qi < 8; qi++) pv[qi] = sS[(ty + 8 * qi) * 65 + j]; // broadcast
            #pragma unroll
            for (int ci = 0; ci < 8; ci++) vv[ci] = sV[j * 256 + tx + 32 * ci]; // stride-1
            #pragma unroll
            for (int qi = 0; qi < 8; qi++)
                #pragma unroll
                for (int ci = 0; ci < 8; ci++)
                    acc[qi][ci] = fmaf(pv[qi], vv[ci], acc[qi][ci]);
        }
        __syncthreads();
    }

    // Epilogue: normalize, gamma-scale, transpose through smem, + x, store
    float linv[8];
    #pragma unroll
    for (int qi = 0; qi < 8; qi++) linv[qi] = 1.f / rsum[ty + 8 * qi];
    float g[8];
    #pragma unroll
    for (int ci = 0; ci < 8; ci++) g[ci] = gamma[tx + 32 * ci];

    #pragma unroll
    for (int qi = 0; qi < 8; qi++)
        #pragma unroll
        for (int ci = 0; ci < 8; ci++)
            sT[(tx + 32 * ci) * 65 + (ty + 8 * qi)] = g[ci] * acc[qi][ci] * linv[qi];
    __syncthreads();

    // [256 c][64 n] -> out[b][c][n0+n] (+x), 128B-coalesced float4
    #pragma unroll
    for (int r = 0; r < 16; r++) {
        int c  = r * 16 + (t >> 4);
        int nl = (t & 15) * 4;
        size_t gi = ((size_t)(b * NI + c)) * NPIX + n0 + nl;
        float4 xv = *reinterpret_cast<const float4*>(x + gi);
        float4 ov;
        ov.x = sT[c * 65 + nl + 0] + xv.x;
        ov.y = sT[c * 65 + nl + 1] + xv.y;
        ov.z = sT[c * 65 + nl + 2] + xv.z;
        ov.w = sT[c * 65 + nl + 3] + xv.w;
        *reinterpret_cast<float4*>(out + gi) = ov;
    }
}

// ---------------------------------------------------------------------------
extern "C" void kernel_launch(void* const* d_in, const int* in_sizes, int n_in,
                              void* d_out, int out_size)
{
    const float* x     = (const float*)d_in[0];
    const float* wq    = (const float*)d_in[1];
    const float* bq    = (const float*)d_in[2];
    const float* wk    = (const float*)d_in[3];
    const float* bk    = (const float*)d_in[4];
    const float* wv    = (const float*)d_in[5];
    const float* bv    = (const float*)d_in[6];
    const float* gamma = (const float*)d_in[7];
    float* out = (float*)d_out;

    cudaFuncSetAttribute(attn_kernel,
                         cudaFuncAttributeMaxDynamicSharedMemorySize,
                         SMEM_FLOATS * (int)sizeof(float));

    dim3 blk(256);
    proj_kernel<<<dim3(32, 1, BS), blk>>>(x, wq, bq, 0);
    proj_kernel<<<dim3(32, 1, BS), blk>>>(x, wk, bk, 1);
    proj_kernel<<<dim3(32, 8, BS), blk>>>(x, wv, bv, 2);
    attn_kernel<<<dim3(NPIX / BM, BS), blk, SMEM_FLOATS * (int)sizeof(float)>>>(x, gamma, out);
}

// round 2
// speedup vs baseline: 1.0688x; 1.0688x over previous
#include <cuda_runtime.h>

#define NI   256
#define QK   32
#define BS   4
#define NPIX 4096
#define BM   64
#define BN   64

// Scratch (device globals: allocation-free contract)
__device__ float g_Q[BS * NPIX * QK];   //  2 MB  [b][n][32]
__device__ float g_K[BS * NPIX * QK];   //  2 MB  [b][n][32]
__device__ float g_V[BS * NPIX * NI];   // 16 MB  [b][n][256]

// ---------------- packed f32x2 helpers (sm_103a FFMA2) ----------------
__device__ __forceinline__ unsigned long long ffma2(unsigned long long a,
                                                    unsigned long long b,
                                                    unsigned long long c) {
    unsigned long long d;
    asm("fma.rn.f32x2 %0, %1, %2, %3;" : "=l"(d) : "l"(a), "l"(b), "l"(c));
    return d;
}
__device__ __forceinline__ unsigned long long fmul2(unsigned long long a,
                                                    unsigned long long b) {
    unsigned long long d;
    asm("mul.rn.f32x2 %0, %1, %2;" : "=l"(d) : "l"(a), "l"(b));
    return d;
}
__device__ __forceinline__ unsigned long long pack2(float lo, float hi) {
    unsigned long long d;
    asm("mov.b64 %0, {%1, %2};" : "=l"(d) : "f"(lo), "f"(hi));
    return d;
}

// ---------------------------------------------------------------------------
// Projection: dst[b][n][o] = sum_c W[o][c] * x[b][c][n] + bias[o]
// mode 0: Q+K fused (blockIdx.y selects), mode 1: V (blockIdx.y = o-tile)
// ---------------------------------------------------------------------------
__global__ __launch_bounds__(256) void proj_kernel(
    const float* __restrict__ x,
    const float* __restrict__ W0, const float* __restrict__ b0,
    const float* __restrict__ W1, const float* __restrict__ b1,
    int mode)
{
    float* dst; int ldo, o0;
    const float* W; const float* bias;
    if (mode == 0) {
        int sub = blockIdx.y;
        dst  = sub ? g_K : g_Q;
        W    = sub ? W1 : W0;
        bias = sub ? b1 : b0;
        ldo = QK; o0 = 0;
    } else {
        dst = g_V; W = W0; bias = b0;
        ldo = NI; o0 = blockIdx.y * 32;
    }

    __shared__ float sX[4352];      // [32][128] compute tile, then [128][33]
    __shared__ float sW[32 * 33];

    const int t  = threadIdx.x;
    const int nx = t & 31;
    const int oy = t >> 5;
    const int b  = blockIdx.z;
    const int n0 = blockIdx.x * 128;

    float acc[4][4];
    #pragma unroll
    for (int i = 0; i < 4; i++)
        #pragma unroll
        for (int j = 0; j < 4; j++) acc[i][j] = 0.f;

    for (int k0 = 0; k0 < NI; k0 += 32) {
        const float4* xp = reinterpret_cast<const float4*>(
            x + ((size_t)(b * NI + k0)) * NPIX + n0);
        #pragma unroll
        for (int r = 0; r < 4; r++) {
            int fi = t + r * 256;
            int kk = fi >> 5, c4 = fi & 31;
            reinterpret_cast<float4*>(sX)[kk * 32 + c4] = xp[(size_t)kk * 1024 + c4];
        }
        #pragma unroll
        for (int r = 0; r < 4; r++) {
            int ei = t + r * 256;
            int o = ei >> 5, kk = ei & 31;
            sW[o * 33 + kk] = W[(size_t)(o0 + o) * NI + k0 + kk];
        }
        __syncthreads();

        #pragma unroll
        for (int kk = 0; kk < 32; kk++) {
            float wf[4], xf[4];
            #pragma unroll
            for (int i = 0; i < 4; i++) wf[i] = sW[(oy + 8 * i) * 33 + kk];
            #pragma unroll
            for (int j = 0; j < 4; j++) xf[j] = sX[kk * 128 + nx + 32 * j];
            #pragma unroll
            for (int i = 0; i < 4; i++)
                #pragma unroll
                for (int j = 0; j < 4; j++)
                    acc[i][j] = fmaf(wf[i], xf[j], acc[i][j]);
        }
        __syncthreads();
    }

    #pragma unroll
    for (int i = 0; i < 4; i++) {
        float bb = bias[o0 + oy + 8 * i];
        #pragma unroll
        for (int j = 0; j < 4; j++)
            sX[(nx + 32 * j) * 33 + oy + 8 * i] = acc[i][j] + bb;
    }
    __syncthreads();

    #pragma unroll
    for (int r = 0; r < 4; r++) {
        int fi = t + r * 256;
        int n = fi >> 3, o4 = (fi & 7) * 4;
        float4 v;
        v.x = sX[n * 33 + o4 + 0];
        v.y = sX[n * 33 + o4 + 1];
        v.z = sX[n * 33 + o4 + 2];
        v.w = sX[n * 33 + o4 + 3];
        reinterpret_cast<float4*>(dst + ((size_t)(b * NPIX + n0 + n)) * ldo + o0)[o4 >> 2] = v;
    }
}

// ---------------------------------------------------------------------------
// Flash attention, f32x2 packed.
// 256 threads = 32(tx) x 8(ty). Thread owns 8 queries (ty+8qi) and 8 channels
// {tx*4..tx*4+3, 128+tx*4..+3} packed as 4 f32x2 accumulators per query.
// smem (floats):
//   sQ [64][36]   @ 0      (2304)
//   sK [64][36]   @ 2304   (2304)
//   rsum @4608, rmax @4672, salpha @4736  (64 each) -> 4800
//   sV [32][256]  @ 4800   (8192)   (one 32-key half at a time)
//   sP [64][132]  @ 12992  (8448)   duplicated {p,p} pairs
// total 21440 floats = 85760 B -> 2 CTAs/SM.
// Epilogue overlays sT[256][68] at base.
// ---------------------------------------------------------------------------
#define SMEM_FLOATS 21440

__global__ __launch_bounds__(256, 2) void attn_kernel(
    const float* __restrict__ x, const float* __restrict__ gamma,
    float* __restrict__ out)
{
    extern __shared__ float sm[];
    float* sQ     = sm;
    float* sK     = sm + 2304;
    float* rsum   = sm + 4608;
    float* rmax   = sm + 4672;
    float* salpha = sm + 4736;
    float* sV     = sm + 4800;
    float* sP     = sm + 12992;
    float* sT     = sm;               // epilogue overlay [256][68]

    const int t  = threadIdx.x;
    const int tx = t & 31;
    const int ty = t >> 5;
    const int b  = blockIdx.y;
    const int n0 = blockIdx.x * BM;

    // Q tile [64][32] -> sQ rows stride 36
    const float* Qb = g_Q + ((size_t)(b * NPIX + n0)) * QK;
    #pragma unroll
    for (int r = 0; r < 8; r++) {
        int e = t + r * 256;
        sQ[(e >> 5) * 36 + (e & 31)] = Qb[e];
    }
    if (t < 64) { rmax[t] = -1e30f; rsum[t] = 0.f; }

    unsigned long long acc2[8][4];
    #pragma unroll
    for (int qi = 0; qi < 8; qi++)
        #pragma unroll
        for (int k = 0; k < 4; k++) acc2[qi][k] = 0ull;

    for (int jt = 0; jt < NPIX / BN; jt++) {
        const int j0 = jt * BN;
        __syncthreads();   // sV/sK free (prev tile fully consumed)

        // K tile [64][32] -> stride 36
        const float* Kb = g_K + ((size_t)(b * NPIX + j0)) * QK;
        #pragma unroll
        for (int r = 0; r < 8; r++) {
            int e = t + r * 256;
            sK[(e >> 5) * 36 + (e & 31)] = Kb[e];
        }
        // V half 0: rows j0..j0+31
        {
            const float4* Vb = reinterpret_cast<const float4*>(
                g_V + ((size_t)(b * NPIX + j0)) * NI);
            #pragma unroll
            for (int r = 0; r < 8; r++) {
                int fi = t + r * 256;
                reinterpret_cast<float4*>(sV)[fi] = Vb[fi];
            }
        }
        __syncthreads();

        // ---- S = Q K^T (scalar FFMA, float4 LDS) ----
        {
            float s0[8], s1[8];
            #pragma unroll
            for (int qi = 0; qi < 8; qi++) { s0[qi] = 0.f; s1[qi] = 0.f; }
            #pragma unroll
            for (int d0 = 0; d0 < 32; d0 += 4) {
                float4 k0 = *reinterpret_cast<const float4*>(&sK[tx * 36 + d0]);
                float4 k1 = *reinterpret_cast<const float4*>(&sK[(tx + 32) * 36 + d0]);
                #pragma unroll
                for (int qi = 0; qi < 8; qi++) {
                    float4 q = *reinterpret_cast<const float4*>(&sQ[(ty + 8 * qi) * 36 + d0]);
                    s0[qi] = fmaf(q.x, k0.x, s0[qi]);
                    s0[qi] = fmaf(q.y, k0.y, s0[qi]);
                    s0[qi] = fmaf(q.z, k0.z, s0[qi]);
                    s0[qi] = fmaf(q.w, k0.w, s0[qi]);
                    s1[qi] = fmaf(q.x, k1.x, s1[qi]);
                    s1[qi] = fmaf(q.y, k1.y, s1[qi]);
                    s1[qi] = fmaf(q.z, k1.z, s1[qi]);
                    s1[qi] = fmaf(q.w, k1.w, s1[qi]);
                }
            }
            // write duplicated {s,s} pairs
            #pragma unroll
            for (int qi = 0; qi < 8; qi++) {
                int row = (ty + 8 * qi) * 132;
                *reinterpret_cast<float2*>(&sP[row + 2 * tx]) =
                    make_float2(s0[qi], s0[qi]);
                *reinterpret_cast<float2*>(&sP[row + 2 * (tx + 32)]) =
                    make_float2(s1[qi], s1[qi]);
            }
        }
        __syncthreads();

        // ---- online softmax: 4 threads per row ----
        {
            int r  = t >> 2;
            int qt = t & 3;
            float* rowp = sP + r * 132 + qt * 32;   // 16 keys, duplicated
            float m = -1e30f;
            #pragma unroll
            for (int k = 0; k < 8; k++) {
                float4 v = *reinterpret_cast<const float4*>(&rowp[k * 4]);
                m = fmaxf(m, fmaxf(v.x, v.z));
            }
            m = fmaxf(m, __shfl_xor_sync(0xffffffffu, m, 1));
            m = fmaxf(m, __shfl_xor_sync(0xffffffffu, m, 2));
            float mo = rmax[r];
            float nm = fmaxf(mo, m);
            float s = 0.f;
            #pragma unroll
            for (int k = 0; k < 8; k++) {
                float4 v = *reinterpret_cast<const float4*>(&rowp[k * 4]);
                float e0 = __expf(v.x - nm);
                float e1 = __expf(v.z - nm);
                *reinterpret_cast<float4*>(&rowp[k * 4]) = make_float4(e0, e0, e1, e1);
                s += e0 + e1;
            }
            s += __shfl_xor_sync(0xffffffffu, s, 1);
            s += __shfl_xor_sync(0xffffffffu, s, 2);
            if (qt == 0) {
                float a = __expf(mo - nm);
                salpha[r] = a;
                rsum[r] = a * rsum[r] + s;
                rmax[r] = nm;
            }
        }
        __syncthreads();

        // ---- rescale acc by alpha ----
        #pragma unroll
        for (int qi = 0; qi < 8; qi++) {
            float a = salpha[ty + 8 * qi];
            unsigned long long a2 = pack2(a, a);
            #pragma unroll
            for (int k = 0; k < 4; k++) acc2[qi][k] = fmul2(acc2[qi][k], a2);
        }

        // ---- PV half 0 ----
        #pragma unroll 4
        for (int j = 0; j < 32; j += 2) {
            ulonglong2 va0 = *reinterpret_cast<const ulonglong2*>(&sV[j * 256 + tx * 4]);
            ulonglong2 va1 = *reinterpret_cast<const ulonglong2*>(&sV[j * 256 + 128 + tx * 4]);
            ulonglong2 vb0 = *reinterpret_cast<const ulonglong2*>(&sV[(j + 1) * 256 + tx * 4]);
            ulonglong2 vb1 = *reinterpret_cast<const ulonglong2*>(&sV[(j + 1) * 256 + 128 + tx * 4]);
            #pragma unroll
            for (int qi = 0; qi < 8; qi++) {
                ulonglong2 P = *reinterpret_cast<const ulonglong2*>(
                    &sP[(ty + 8 * qi) * 132 + 2 * j]);
                acc2[qi][0] = ffma2(P.x, va0.x, acc2[qi][0]);
                acc2[qi][1] = ffma2(P.x, va0.y, acc2[qi][1]);
                acc2[qi][2] = ffma2(P.x, va1.x, acc2[qi][2]);
                acc2[qi][3] = ffma2(P.x, va1.y, acc2[qi][3]);
                acc2[qi][0] = ffma2(P.y, vb0.x, acc2[qi][0]);
                acc2[qi][1] = ffma2(P.y, vb0.y, acc2[qi][1]);
                acc2[qi][2] = ffma2(P.y, vb1.x, acc2[qi][2]);
                acc2[qi][3] = ffma2(P.y, vb1.y, acc2[qi][3]);
            }
        }
        __syncthreads();

        // V half 1: rows j0+32..j0+63
        {
            const float4* Vb = reinterpret_cast<const float4*>(
                g_V + ((size_t)(b * NPIX + j0 + 32)) * NI);
            #pragma unroll
            for (int r = 0; r < 8; r++) {
                int fi = t + r * 256;
                reinterpret_cast<float4*>(sV)[fi] = Vb[fi];
            }
        }
        __syncthreads();

        // ---- PV half 1 ----
        #pragma unroll 4
        for (int j = 32; j < 64; j += 2) {
            int jr = j - 32;
            ulonglong2 va0 = *reinterpret_cast<const ulonglong2*>(&sV[jr * 256 + tx * 4]);
            ulonglong2 va1 = *reinterpret_cast<const ulonglong2*>(&sV[jr * 256 + 128 + tx * 4]);
            ulonglong2 vb0 = *reinterpret_cast<const ulonglong2*>(&sV[(jr + 1) * 256 + tx * 4]);
            ulonglong2 vb1 = *reinterpret_cast<const ulonglong2*>(&sV[(jr + 1) * 256 + 128 + tx * 4]);
            #pragma unroll
            for (int qi = 0; qi < 8; qi++) {
                ulonglong2 P = *reinterpret_cast<const ulonglong2*>(
                    &sP[(ty + 8 * qi) * 132 + 2 * j]);
                acc2[qi][0] = ffma2(P.x, va0.x, acc2[qi][0]);
                acc2[qi][1] = ffma2(P.x, va0.y, acc2[qi][1]);
                acc2[qi][2] = ffma2(P.x, va1.x, acc2[qi][2]);
                acc2[qi][3] = ffma2(P.x, va1.y, acc2[qi][3]);
                acc2[qi][0] = ffma2(P.y, vb0.x, acc2[qi][0]);
                acc2[qi][1] = ffma2(P.y, vb0.y, acc2[qi][1]);
                acc2[qi][2] = ffma2(P.y, vb1.x, acc2[qi][2]);
                acc2[qi][3] = ffma2(P.y, vb1.y, acc2[qi][3]);
            }
        }
    }

    // ---- epilogue ----
    float linv[8];
    #pragma unroll
    for (int qi = 0; qi < 8; qi++) linv[qi] = 1.f / rsum[ty + 8 * qi];
    float4 g0 = *reinterpret_cast<const float4*>(&gamma[tx * 4]);
    float4 g1 = *reinterpret_cast<const float4*>(&gamma[128 + tx * 4]);
    __syncthreads();   // everyone past PV / rsum reads before sT overlay

    #pragma unroll
    for (int qi = 0; qi < 8; qi++) {
        int q = ty + 8 * qi;
        float2 f0 = *reinterpret_cast<float2*>(&acc2[qi][0]);
        float2 f1 = *reinterpret_cast<float2*>(&acc2[qi][1]);
        float2 f2 = *reinterpret_cast<float2*>(&acc2[qi][2]);
        float2 f3 = *reinterpret_cast<float2*>(&acc2[qi][3]);
        int c = tx * 4;
        sT[(c + 0) * 68 + q] = g0.x * f0.x * linv[qi];
        sT[(c + 1) * 68 + q] = g0.y * f0.y * linv[qi];
        sT[(c + 2) * 68 + q] = g0.z * f1.x * linv[qi];
        sT[(c + 3) * 68 + q] = g0.w * f1.y * linv[qi];
        sT[(c + 128) * 68 + q] = g1.x * f2.x * linv[qi];
        sT[(c + 129) * 68 + q] = g1.y * f2.y * linv[qi];
        sT[(c + 130) * 68 + q] = g1.z * f3.x * linv[qi];
        sT[(c + 131) * 68 + q] = g1.w * f3.y * linv[qi];
    }
    __syncthreads();

    #pragma unroll
    for (int r = 0; r < 16; r++) {
        int c  = r * 16 + (t >> 4);
        int nl = (t & 15) * 4;
        size_t gi = ((size_t)(b * NI + c)) * NPIX + n0 + nl;
        float4 xv = *reinterpret_cast<const float4*>(x + gi);
        float4 ov;
        ov.x = sT[c * 68 + nl + 0] + xv.x;
        ov.y = sT[c * 68 + nl + 1] + xv.y;
        ov.z = sT[c * 68 + nl + 2] + xv.z;
        ov.w = sT[c * 68 + nl + 3] + xv.w;
        *reinterpret_cast<float4*>(out + gi) = ov;
    }
}

// ---------------------------------------------------------------------------
extern "C" void kernel_launch(void* const* d_in, const int* in_sizes, int n_in,
                              void* d_out, int out_size)
{
    const float* x     = (const float*)d_in[0];
    const float* wq    = (const float*)d_in[1];
    const float* bq    = (const float*)d_in[2];
    const float* wk    = (const float*)d_in[3];
    const float* bk    = (const float*)d_in[4];
    const float* wv    = (const float*)d_in[5];
    const float* bv    = (const float*)d_in[6];
    const float* gamma = (const float*)d_in[7];
    float* out = (float*)d_out;

    cudaFuncSetAttribute(attn_kernel,
                         cudaFuncAttributeMaxDynamicSharedMemorySize,
                         SMEM_FLOATS * (int)sizeof(float));

    dim3 blk(256);
    proj_kernel<<<dim3(32, 2, BS), blk>>>(x, wq, bq, wk, bk, 0);
    proj_kernel<<<dim3(32, 8, BS), blk>>>(x, wv, bv, nullptr, nullptr, 1);
    attn_kernel<<<dim3(NPIX / BM, BS), blk, SMEM_FLOATS * (int)sizeof(float)>>>(x, gamma, out);
}

// round 4
// speedup vs baseline: 4.5844x; 4.2893x over previous
#include <cuda_runtime.h>
#include <cuda_bf16.h>
#include <cstdint>

#define NI   256
#define QK   32
#define BS   4
#define NPIX 4096
#define BM   128
#define BN   64
#define NT   (NPIX / BN)

// ---------------- scratch (bf16) ----------------
// Q rows: [Qh(32) | Qh(32) | Ql(32)]   K rows: [Kh(32) | Kl(32) | Kh(32)]
__device__ __nv_bfloat16 g_Q[BS * NPIX * 96];
__device__ __nv_bfloat16 g_K[BS * NPIX * 96];
__device__ __nv_bfloat16 g_V[BS * NI * NPIX];   // [b][c][n]

// ---------------- helpers ----------------
__device__ __forceinline__ uint32_t smem_u32(const void* p) {
    uint32_t a;
    asm("{ .reg .u64 t; cvta.to.shared.u64 t, %1; cvt.u32.u64 %0, t; }" : "=r"(a) : "l"(p));
    return a;
}
__device__ __forceinline__ uint32_t cvt_bf16x2(float lo, float hi) {
    uint32_t r;
    asm("cvt.rn.bf16x2.f32 %0, %1, %2;" : "=r"(r) : "f"(hi), "f"(lo));
    return r;
}
__device__ __forceinline__ void ldsm4(uint32_t* r, uint32_t addr) {
    asm volatile("ldmatrix.sync.aligned.m8n8.x4.shared.b16 {%0,%1,%2,%3}, [%4];"
        : "=r"(r[0]), "=r"(r[1]), "=r"(r[2]), "=r"(r[3]) : "r"(addr));
}
__device__ __forceinline__ void mma16816(float* d, const uint32_t* a,
                                         uint32_t b0, uint32_t b1) {
    asm volatile("mma.sync.aligned.m16n8k16.row.col.f32.bf16.bf16.f32 "
        "{%0,%1,%2,%3}, {%4,%5,%6,%7}, {%8,%9}, {%0,%1,%2,%3};"
        : "+f"(d[0]), "+f"(d[1]), "+f"(d[2]), "+f"(d[3])
        : "r"(a[0]), "r"(a[1]), "r"(a[2]), "r"(a[3]), "r"(b0), "r"(b1));
}
#define STS128X(a, r0, r1, r2, r3) \
    asm volatile("st.shared.v4.b32 [%0], {%1,%2,%3,%4};" :: "r"(a), "r"(r0), "r"(r1), "r"(r2), "r"(r3) : "memory")
#define STS32X(a, r0) \
    asm volatile("st.shared.b32 [%0], %1;" :: "r"(a), "r"(r0) : "memory")

// ---------------------------------------------------------------------------
// Q/K projection -> hi/lo bf16 split, 96-wide rows, layout [b][n][96]
// ---------------------------------------------------------------------------
__global__ __launch_bounds__(256) void proj_qk_kernel(
    const float* __restrict__ x,
    const float* __restrict__ Wq, const float* __restrict__ bq,
    const float* __restrict__ Wk, const float* __restrict__ bk)
{
    __shared__ float sX[4352];
    __shared__ float sW[32 * 33];
    __shared__ __align__(16) __nv_bfloat16 sOb[128 * 104];  // [n][96] pad 104

    const int t = threadIdx.x, nx = t & 31, oy = t >> 5;
    const int b = blockIdx.z, n0 = blockIdx.x * 128;
    const int sub = blockIdx.y;
    const float* W    = sub ? Wk : Wq;
    const float* bias = sub ? bk : bq;
    __nv_bfloat16* dst = sub ? g_K : g_Q;

    float acc[4][4];
    #pragma unroll
    for (int i = 0; i < 4; i++)
        #pragma unroll
        for (int j = 0; j < 4; j++) acc[i][j] = 0.f;

    for (int k0 = 0; k0 < NI; k0 += 32) {
        const float4* xp = reinterpret_cast<const float4*>(
            x + ((size_t)(b * NI + k0)) * NPIX + n0);
        #pragma unroll
        for (int r = 0; r < 4; r++) {
            int fi = t + r * 256;
            reinterpret_cast<float4*>(sX)[(fi >> 5) * 32 + (fi & 31)] =
                xp[(size_t)(fi >> 5) * 1024 + (fi & 31)];
        }
        #pragma unroll
        for (int r = 0; r < 4; r++) {
            int ei = t + r * 256;
            sW[(ei >> 5) * 33 + (ei & 31)] = W[(size_t)(ei >> 5) * NI + k0 + (ei & 31)];
        }
        __syncthreads();
        #pragma unroll
        for (int kk = 0; kk < 32; kk++) {
            float wf[4], xf[4];
            #pragma unroll
            for (int i = 0; i < 4; i++) wf[i] = sW[(oy + 8 * i) * 33 + kk];
            #pragma unroll
            for (int j = 0; j < 4; j++) xf[j] = sX[kk * 128 + nx + 32 * j];
            #pragma unroll
            for (int i = 0; i < 4; i++)
                #pragma unroll
                for (int j = 0; j < 4; j++)
                    acc[i][j] = fmaf(wf[i], xf[j], acc[i][j]);
        }
        __syncthreads();
    }

    #pragma unroll
    for (int i = 0; i < 4; i++) {
        float bb = bias[oy + 8 * i];
        int o = oy + 8 * i;
        #pragma unroll
        for (int j = 0; j < 4; j++) {
            float f = acc[i][j] + bb;
            __nv_bfloat16 hi = __float2bfloat16(f);
            __nv_bfloat16 lo = __float2bfloat16(f - __bfloat162float(hi));
            int n = nx + 32 * j;
            if (sub == 0) {             // Q: [Qh | Qh | Ql]
                sOb[n * 104 + o]      = hi;
                sOb[n * 104 + 32 + o] = hi;
                sOb[n * 104 + 64 + o] = lo;
            } else {                    // K: [Kh | Kl | Kh]
                sOb[n * 104 + o]      = hi;
                sOb[n * 104 + 32 + o] = lo;
                sOb[n * 104 + 64 + o] = hi;
            }
        }
    }
    __syncthreads();

    uint4* dq = reinterpret_cast<uint4*>(dst + (size_t)(b * NPIX + n0) * 96);
    #pragma unroll
    for (int r = 0; r < 6; r++) {
        int fi = t + r * 256;
        int row = fi / 12, c = fi % 12;
        dq[fi] = *reinterpret_cast<const uint4*>(sOb + row * 104 + c * 8);
    }
}

// ---------------------------------------------------------------------------
// V projection -> bf16 channel-major [b][c][n]
// ---------------------------------------------------------------------------
__global__ __launch_bounds__(256) void proj_v_kernel(
    const float* __restrict__ x, const float* __restrict__ W,
    const float* __restrict__ bias)
{
    __shared__ float sX[4352];
    __shared__ float sW[32 * 33];

    const int t = threadIdx.x, nx = t & 31, oy = t >> 5;
    const int b = blockIdx.z, n0 = blockIdx.x * 128, o0 = blockIdx.y * 32;

    float acc[4][4];
    #pragma unroll
    for (int i = 0; i < 4; i++)
        #pragma unroll
        for (int j = 0; j < 4; j++) acc[i][j] = 0.f;

    for (int k0 = 0; k0 < NI; k0 += 32) {
        const float4* xp = reinterpret_cast<const float4*>(
            x + ((size_t)(b * NI + k0)) * NPIX + n0);
        #pragma unroll
        for (int r = 0; r < 4; r++) {
            int fi = t + r * 256;
            reinterpret_cast<float4*>(sX)[(fi >> 5) * 32 + (fi & 31)] =
                xp[(size_t)(fi >> 5) * 1024 + (fi & 31)];
        }
        #pragma unroll
        for (int r = 0; r < 4; r++) {
            int ei = t + r * 256;
            sW[(ei >> 5) * 33 + (ei & 31)] =
                W[(size_t)(o0 + (ei >> 5)) * NI + k0 + (ei & 31)];
        }
        __syncthreads();
        #pragma unroll
        for (int kk = 0; kk < 32; kk++) {
            float wf[4], xf[4];
            #pragma unroll
            for (int i = 0; i < 4; i++) wf[i] = sW[(oy + 8 * i) * 33 + kk];
            #pragma unroll
            for (int j = 0; j < 4; j++) xf[j] = sX[kk * 128 + nx + 32 * j];
            #pragma unroll
            for (int i = 0; i < 4; i++)
                #pragma unroll
                for (int j = 0; j < 4; j++)
                    acc[i][j] = fmaf(wf[i], xf[j], acc[i][j]);
        }
        __syncthreads();
    }

    #pragma unroll
    for (int i = 0; i < 4; i++) {
        float bb = bias[o0 + oy + 8 * i];
        #pragma unroll
        for (int j = 0; j < 4; j++)
            g_V[(size_t)(b * NI + o0 + oy + 8 * i) * NPIX + n0 + nx + 32 * j] =
                __float2bfloat16(acc[i][j] + bb);
    }
}

// ---------------------------------------------------------------------------
// mma.sync (HMMA bf16) flash attention. CTA = 128 queries, 256 threads.
// Warps: warp_m = w&3 (32-query row band), warp_n/warp_c = w>>2.
// MMA1: S[128,64] (warp: 32q x 32j, k=96). MMA2: O[128,256] (warp: 32q x 128c).
// smem byte offsets (all 16B aligned):
//   sQ [128][96+pad] stride 208  @ 0       26624
//   sK [ 64][96+pad] stride 208  @ 26624   13312
//   sV [256][64+pad] stride 144  @ 39936   36864
//   sP [128][64+pad] stride 144  @ 76800   18432
//   lpart [2][128] f32           @ 95232   1024
// ---------------------------------------------------------------------------
#define OFF_Q 0
#define OFF_K 26624
#define OFF_V 39936
#define OFF_P 76800
#define OFF_L 95232
#define SMEM_BYTES (OFF_L + 1024)

__global__ __launch_bounds__(256, 1) void attn_kernel(
    const float* __restrict__ x, const float* __restrict__ gamma,
    float* __restrict__ out)
{
    extern __shared__ __align__(16) char smraw[];
    const uint32_t sb = smem_u32(smraw);

    const int tid = threadIdx.x;
    const int w = tid >> 5, lane = tid & 31;
    const int warp_m = w & 3, warp_n = w >> 2;      // warp_n == warp_c
    const int b = blockIdx.y, n0 = blockIdx.x * BM;

    // ldmatrix lane-address components
    const int a_r = (lane & 7) + (lane & 8);            // A-type row
    const int a_k = (lane & 16) >> 1;                    // A-type k off (0/8)
    const int b_r = (lane & 7) + ((lane & 16) >> 1);     // B-type row
    const int b_k = lane & 8;                            // B-type k off

    float* lpart = reinterpret_cast<float*>(smraw + OFF_L);

    // ---- load Q tile [128][96] ----
    {
        const uint4* Qg = reinterpret_cast<const uint4*>(
            g_Q + (size_t)(b * NPIX + n0) * 96);
        #pragma unroll
        for (int r = 0; r < 6; r++) {
            int fi = tid + r * 256;
            int row = fi / 12, c = fi % 12;
            uint4 v = Qg[fi];
            STS128X(sb + OFF_Q + row * 208 + c * 16, v.x, v.y, v.z, v.w);
        }
    }

    float oacc[2][16][4];
    #pragma unroll
    for (int mi = 0; mi < 2; mi++)
        #pragma unroll
        for (int nt = 0; nt < 16; nt++)
            #pragma unroll
            for (int k = 0; k < 4; k++) oacc[mi][nt][k] = 0.f;
    float lacc[2][2] = {{0.f, 0.f}, {0.f, 0.f}};

    // per-thread ldmatrix byte offsets
    const uint32_t qa_off = sb + OFF_Q + (uint32_t)(warp_m * 32) * 208 + a_r * 208 + a_k * 2;
    const uint32_t kb_off = sb + OFF_K + (uint32_t)(warp_n * 32) * 208 + b_r * 208 + b_k * 2;
    const uint32_t pa_off = sb + OFF_P + (uint32_t)(warp_m * 32) * 144 + a_r * 144 + a_k * 2;
    const uint32_t vb_off = sb + OFF_V + (uint32_t)(warp_n * 128) * 144 + b_r * 144 + b_k * 2;

    #pragma unroll 1
    for (int jt = 0; jt < NT; jt++) {
        const int j0 = jt * BN;
        if (jt) __syncthreads();       // prev MMA2 done with sV/sP; sK free

        // ---- load K tile [64][96] ----
        {
            const uint4* Kg = reinterpret_cast<const uint4*>(
                g_K + (size_t)(b * NPIX + j0) * 96);
            #pragma unroll
            for (int r = 0; r < 3; r++) {
                int fi = tid + r * 256;
                int row = fi / 12, c = fi % 12;
                uint4 v = Kg[fi];
                STS128X(sb + OFF_K + row * 208 + c * 16, v.x, v.y, v.z, v.w);
            }
        }
        // ---- load V tile [256 c][64 j] ----
        {
            const uint4* Vg = reinterpret_cast<const uint4*>(g_V) +
                (size_t)b * NI * (NPIX / 8) + (j0 >> 3);
            #pragma unroll
            for (int r = 0; r < 8; r++) {
                int fi = tid + r * 256;
                int c = fi >> 3, g = fi & 7;
                uint4 v = Vg[(size_t)c * (NPIX / 8) + g];
                STS128X(sb + OFF_V + c * 144 + g * 16, v.x, v.y, v.z, v.w);
            }
        }
        __syncthreads();

        // ---- MMA1: S(32q x 32j per warp), k = 96 ----
        float sacc[2][4][4];
        #pragma unroll
        for (int mi = 0; mi < 2; mi++)
            #pragma unroll
            for (int ni = 0; ni < 4; ni++)
                #pragma unroll
                for (int k = 0; k < 4; k++) sacc[mi][ni][k] = 0.f;

        #pragma unroll
        for (int ks = 0; ks < 6; ks++) {
            uint32_t af[2][4], bf[2][4];
            #pragma unroll
            for (int mi = 0; mi < 2; mi++)
                ldsm4(af[mi], qa_off + mi * (16 * 208) + ks * 32);
            #pragma unroll
            for (int np = 0; np < 2; np++)
                ldsm4(bf[np], kb_off + np * (16 * 208) + ks * 32);
            #pragma unroll
            for (int mi = 0; mi < 2; mi++)
                #pragma unroll
                for (int ni = 0; ni < 4; ni++)
                    mma16816(sacc[mi][ni], af[mi], bf[ni >> 1][(ni & 1) * 2],
                             bf[ni >> 1][(ni & 1) * 2 + 1]);
        }

        // ---- exp + pack P to smem ----
        {
            const int q0 = warp_m * 32 + (lane >> 2);
            const int c0 = warp_n * 32 + 2 * (lane & 3);
            #pragma unroll
            for (int mi = 0; mi < 2; mi++) {
                uint32_t rowa = sb + OFF_P + (uint32_t)(q0 + mi * 16) * 144 + c0 * 2;
                #pragma unroll
                for (int ni = 0; ni < 4; ni++) {
                    float e0 = __expf(sacc[mi][ni][0]);
                    float e1 = __expf(sacc[mi][ni][1]);
                    float e2 = __expf(sacc[mi][ni][2]);
                    float e3 = __expf(sacc[mi][ni][3]);
                    lacc[mi][0] += e0 + e1;
                    lacc[mi][1] += e2 + e3;
                    STS32X(rowa + ni * 16, cvt_bf16x2(e0, e1));
                    STS32X(rowa + 8 * 144 + ni * 16, cvt_bf16x2(e2, e3));
                }
            }
        }
        __syncthreads();

        // ---- MMA2: O += P @ V^T (warp: 32q x 128c, k = 64) ----
        #pragma unroll
        for (int ks = 0; ks < 4; ks++) {
            uint32_t af[2][4];
            #pragma unroll
            for (int mi = 0; mi < 2; mi++)
                ldsm4(af[mi], pa_off + mi * (16 * 144) + ks * 32);
            #pragma unroll
            for (int ntp = 0; ntp < 8; ntp++) {
                uint32_t bf[4];
                ldsm4(bf, vb_off + ntp * (16 * 144) + ks * 32);
                #pragma unroll
                for (int mi = 0; mi < 2; mi++) {
                    mma16816(oacc[mi][2 * ntp],     af[mi], bf[0], bf[1]);
                    mma16816(oacc[mi][2 * ntp + 1], af[mi], bf[2], bf[3]);
                }
            }
        }
    }

    // ---- row-sum reduce ----
    #pragma unroll
    for (int mi = 0; mi < 2; mi++)
        #pragma unroll
        for (int rh = 0; rh < 2; rh++) {
            float v = lacc[mi][rh];
            v += __shfl_xor_sync(0xffffffffu, v, 1);
            v += __shfl_xor_sync(0xffffffffu, v, 2);
            lacc[mi][rh] = v;
        }
    __syncthreads();
    if ((lane & 3) == 0) {
        #pragma unroll
        for (int mi = 0; mi < 2; mi++)
            #pragma unroll
            for (int rh = 0; rh < 2; rh++)
                lpart[warp_n * 128 + warp_m * 32 + mi * 16 + (lane >> 2) + 8 * rh] =
                    lacc[mi][rh];
    }
    __syncthreads();

    float linv[2][2];
    #pragma unroll
    for (int mi = 0; mi < 2; mi++)
        #pragma unroll
        for (int rh = 0; rh < 2; rh++) {
            int row = warp_m * 32 + mi * 16 + (lane >> 2) + 8 * rh;
            linv[mi][rh] = 1.f / (lpart[row] + lpart[128 + row]);
        }

    // ---- epilogue: out = gamma*O/l + x ----
    #pragma unroll
    for (int mi = 0; mi < 2; mi++) {
        int q0 = n0 + warp_m * 32 + mi * 16 + (lane >> 2);
        #pragma unroll
        for (int nt = 0; nt < 16; nt++) {
            int c0 = warp_n * 128 + nt * 8 + 2 * (lane & 3);
            float ga = gamma[c0], gb = gamma[c0 + 1];
            size_t i00 = (size_t)(b * NI + c0) * NPIX + q0;
            out[i00]            = ga * oacc[mi][nt][0] * linv[mi][0] + x[i00];
            out[i00 + NPIX]     = gb * oacc[mi][nt][1] * linv[mi][0] + x[i00 + NPIX];
            out[i00 + 8]        = ga * oacc[mi][nt][2] * linv[mi][1] + x[i00 + 8];
            out[i00 + NPIX + 8] = gb * oacc[mi][nt][3] * linv[mi][1] + x[i00 + NPIX + 8];
        }
    }
}

// ---------------------------------------------------------------------------
extern "C" void kernel_launch(void* const* d_in, const int* in_sizes, int n_in,
                              void* d_out, int out_size)
{
    const float* x     = (const float*)d_in[0];
    const float* wq    = (const float*)d_in[1];
    const float* bq    = (const float*)d_in[2];
    const float* wk    = (const float*)d_in[3];
    const float* bk    = (const float*)d_in[4];
    const float* wv    = (const float*)d_in[5];
    const float* bv    = (const float*)d_in[6];
    const float* gamma = (const float*)d_in[7];
    float* out = (float*)d_out;

    cudaFuncSetAttribute(attn_kernel,
                         cudaFuncAttributeMaxDynamicSharedMemorySize, SMEM_BYTES);

    dim3 blk(256);
    proj_qk_kernel<<<dim3(32, 2, BS), blk>>>(x, wq, bq, wk, bk);
    proj_v_kernel<<<dim3(32, 8, BS), blk>>>(x, wv, bv);
    attn_kernel<<<dim3(NPIX / BM, BS), blk, SMEM_BYTES>>>(x, gamma, out);
}

// round 7
// speedup vs baseline: 7.1069x; 1.5502x over previous
#include <cuda_runtime.h>
#include <cuda_bf16.h>
#include <cuda_fp16.h>
#include <cstdint>

#define NI   256
#define QK   32
#define BS   4
#define NPIX 4096
#define BM   128
#define BN   64
#define NT   (NPIX / BN)

// ---------------- scratch (16B-aligned: vectorized access) ----------------
__device__ __align__(16) __half         g_Q[BS * NPIX * 32];    // [b][n][32] fp16
__device__ __align__(16) __half         g_K[BS * NPIX * 32];    // [b][n][32] fp16
__device__ __align__(16) __nv_bfloat16  g_V[BS * NI * NPIX];    // [b][c][n] bf16
__device__ __align__(16) __nv_bfloat16  g_Wv[NI * NI];          // V weights bf16

// ---------------- helpers ----------------
__device__ __forceinline__ uint32_t smem_u32(const void* p) {
    uint32_t a;
    asm("{ .reg .u64 t; cvta.to.shared.u64 t, %1; cvt.u32.u64 %0, t; }" : "=r"(a) : "l"(p));
    return a;
}
__device__ __forceinline__ uint32_t cvt_bf16x2(float lo, float hi) {
    uint32_t r;
    asm("cvt.rn.bf16x2.f32 %0, %1, %2;" : "=r"(r) : "f"(hi), "f"(lo));
    return r;
}
__device__ __forceinline__ void ldsm4(uint32_t* r, uint32_t addr) {
    asm volatile("ldmatrix.sync.aligned.m8n8.x4.shared.b16 {%0,%1,%2,%3}, [%4];"
        : "=r"(r[0]), "=r"(r[1]), "=r"(r[2]), "=r"(r[3]) : "r"(addr));
}
__device__ __forceinline__ void mma_bf16(float* d, const uint32_t* a,
                                         uint32_t b0, uint32_t b1) {
    asm volatile("mma.sync.aligned.m16n8k16.row.col.f32.bf16.bf16.f32 "
        "{%0,%1,%2,%3}, {%4,%5,%6,%7}, {%8,%9}, {%0,%1,%2,%3};"
        : "+f"(d[0]), "+f"(d[1]), "+f"(d[2]), "+f"(d[3])
        : "r"(a[0]), "r"(a[1]), "r"(a[2]), "r"(a[3]), "r"(b0), "r"(b1));
}
__device__ __forceinline__ void mma_fp16(float* d, const uint32_t* a,
                                         uint32_t b0, uint32_t b1) {
    asm volatile("mma.sync.aligned.m16n8k16.row.col.f32.f16.f16.f32 "
        "{%0,%1,%2,%3}, {%4,%5,%6,%7}, {%8,%9}, {%0,%1,%2,%3};"
        : "+f"(d[0]), "+f"(d[1]), "+f"(d[2]), "+f"(d[3])
        : "r"(a[0]), "r"(a[1]), "r"(a[2]), "r"(a[3]), "r"(b0), "r"(b1));
}
#define STS128X(a, r0, r1, r2, r3) \
    asm volatile("st.shared.v4.b32 [%0], {%1,%2,%3,%4};" :: "r"(a), "r"(r0), "r"(r1), "r"(r2), "r"(r3) : "memory")
#define STS32X(a, r0) \
    asm volatile("st.shared.b32 [%0], %1;" :: "r"(a), "r"(r0) : "memory")
__device__ __forceinline__ void cp16(uint32_t dst, const void* src) {
    asm volatile("cp.async.cg.shared.global [%0], [%1], 16;" :: "r"(dst), "l"(src) : "memory");
}
#define CP_COMMIT() asm volatile("cp.async.commit_group;" ::: "memory")
#define CP_WAIT0()  asm volatile("cp.async.wait_group 0;" ::: "memory")

// ---------------------------------------------------------------------------
// W_v -> bf16 convert (one-time tiny kernel)
// ---------------------------------------------------------------------------
__global__ void conv_w_kernel(const float* __restrict__ W) {
    int i = blockIdx.x * 256 + threadIdx.x;          // 16384 float4s
    float4 v = reinterpret_cast<const float4*>(W)[i];
    uint2 o;
    o.x = cvt_bf16x2(v.x, v.y);
    o.y = cvt_bf16x2(v.z, v.w);
    reinterpret_cast<uint2*>(g_Wv)[i] = o;
}

// ---------------------------------------------------------------------------
// Fused Q+K projection (exact fp32 FFMA), output fp16 [b][n][32]
// ---------------------------------------------------------------------------
__global__ __launch_bounds__(256) void proj_qk_kernel(
    const float* __restrict__ x,
    const float* __restrict__ Wq, const float* __restrict__ bq,
    const float* __restrict__ Wk, const float* __restrict__ bk)
{
    __shared__ float sX[4352];
    __shared__ float sWq[32 * 33];
    __shared__ float sWk[32 * 33];
    __shared__ __align__(16) __half sObq[128 * 40];
    __shared__ __align__(16) __half sObk[128 * 40];

    const int t = threadIdx.x, nx = t & 31, oy = t >> 5;
    const int b = blockIdx.z, n0 = blockIdx.x * 128;

    float aq[4][4], ak[4][4];
    #pragma unroll
    for (int i = 0; i < 4; i++)
        #pragma unroll
        for (int j = 0; j < 4; j++) { aq[i][j] = 0.f; ak[i][j] = 0.f; }

    for (int k0 = 0; k0 < NI; k0 += 32) {
        const float4* xp = reinterpret_cast<const float4*>(
            x + ((size_t)(b * NI + k0)) * NPIX + n0);
        #pragma unroll
        for (int r = 0; r < 4; r++) {
            int fi = t + r * 256;
            reinterpret_cast<float4*>(sX)[(fi >> 5) * 32 + (fi & 31)] =
                xp[(size_t)(fi >> 5) * 1024 + (fi & 31)];
        }
        #pragma unroll
        for (int r = 0; r < 4; r++) {
            int ei = t + r * 256;
            sWq[(ei >> 5) * 33 + (ei & 31)] = Wq[(size_t)(ei >> 5) * NI + k0 + (ei & 31)];
            sWk[(ei >> 5) * 33 + (ei & 31)] = Wk[(size_t)(ei >> 5) * NI + k0 + (ei & 31)];
        }
        __syncthreads();
        #pragma unroll
        for (int kk = 0; kk < 32; kk++) {
            float wq[4], wk[4], xf[4];
            #pragma unroll
            for (int i = 0; i < 4; i++) {
                wq[i] = sWq[(oy + 8 * i) * 33 + kk];
                wk[i] = sWk[(oy + 8 * i) * 33 + kk];
            }
            #pragma unroll
            for (int j = 0; j < 4; j++) xf[j] = sX[kk * 128 + nx + 32 * j];
            #pragma unroll
            for (int i = 0; i < 4; i++)
                #pragma unroll
                for (int j = 0; j < 4; j++) {
                    aq[i][j] = fmaf(wq[i], xf[j], aq[i][j]);
                    ak[i][j] = fmaf(wk[i], xf[j], ak[i][j]);
                }
        }
        __syncthreads();
    }

    #pragma unroll
    for (int i = 0; i < 4; i++) {
        int o = oy + 8 * i;
        float bbq = bq[o], bbk = bk[o];
        #pragma unroll
        for (int j = 0; j < 4; j++) {
            int n = nx + 32 * j;
            sObq[n * 40 + o] = __float2half_rn(aq[i][j] + bbq);
            sObk[n * 40 + o] = __float2half_rn(ak[i][j] + bbk);
        }
    }
    __syncthreads();

    uint4* dq = reinterpret_cast<uint4*>(g_Q + (size_t)(b * NPIX + n0) * 32);
    uint4* dk = reinterpret_cast<uint4*>(g_K + (size_t)(b * NPIX + n0) * 32);
    #pragma unroll
    for (int r = 0; r < 2; r++) {
        int fi = t + r * 256;
        int row = fi >> 2, c = fi & 3;
        dq[fi] = *reinterpret_cast<const uint4*>(sObq + row * 40 + c * 8);
        dk[fi] = *reinterpret_cast<const uint4*>(sObk + row * 40 + c * 8);
    }
}

// ---------------------------------------------------------------------------
// V projection via bf16 HMMA: V[c][n] = sum_k Wv[c][k] x[k][n] + bv[c]
// CTA: m = 256 c, n-tile = 64. 8 warps: warp w -> c band w*32.
// smem: A [256][40]bf16 @0 (20480) | B [64][40]bf16 @20480 (5120)
//       staging D [256][72]bf16 @0 (36864, overlaid after MMAs; 144B rows)
// ---------------------------------------------------------------------------
#define PV_A 0
#define PV_B 20480
#define PV_D 0
#define PV_SMEM 36864

__global__ __launch_bounds__(256) void proj_v_kernel(
    const float* __restrict__ x, const float* __restrict__ bv)
{
    __shared__ __align__(16) char smv[PV_SMEM];
    const uint32_t sb = smem_u32(smv);

    const int t = threadIdx.x, w = t >> 5, lane = t & 31;
    const int b = blockIdx.y, n0 = blockIdx.x * 64;

    const int a_r = (lane & 7) + (lane & 8);
    const int a_k = (lane & 16) >> 1;
    const int b_r = (lane & 7) + ((lane & 16) >> 1);
    const int b_k = lane & 8;

    float acc[2][8][4];
    #pragma unroll
    for (int mi = 0; mi < 2; mi++)
        #pragma unroll
        for (int nt = 0; nt < 8; nt++)
            #pragma unroll
            for (int k = 0; k < 4; k++) acc[mi][nt][k] = 0.f;

    const uint32_t aa = sb + PV_A + (uint32_t)(w * 32 + a_r) * 80 + a_k * 2;
    const uint32_t bb = sb + PV_B + (uint32_t)b_r * 80 + b_k * 2;

    for (int kc = 0; kc < NI; kc += 32) {
        if (kc) __syncthreads();
        // A chunk: Wv rows [256][kc..kc+31] bf16
        #pragma unroll
        for (int r = 0; r < 4; r++) {
            int fi = t + r * 256;
            int row = fi >> 2, c = fi & 3;
            uint4 v = *reinterpret_cast<const uint4*>(g_Wv + row * NI + kc + c * 8);
            STS128X(sb + PV_A + row * 80 + c * 16, v.x, v.y, v.z, v.w);
        }
        // B chunk: x [kc..kc+31][n0..n0+63] fp32 -> transpose bf16 [n][k]
        #pragma unroll
        for (int r = 0; r < 2; r++) {
            int fi = t + r * 256;
            int kk = fi >> 4, f4 = fi & 15;
            float4 xv = *reinterpret_cast<const float4*>(
                x + (size_t)(b * NI + kc + kk) * NPIX + n0 + f4 * 4);
            __nv_bfloat16* bp = reinterpret_cast<__nv_bfloat16*>(smv + PV_B);
            bp[(f4 * 4 + 0) * 40 + kk] = __float2bfloat16(xv.x);
            bp[(f4 * 4 + 1) * 40 + kk] = __float2bfloat16(xv.y);
            bp[(f4 * 4 + 2) * 40 + kk] = __float2bfloat16(xv.z);
            bp[(f4 * 4 + 3) * 40 + kk] = __float2bfloat16(xv.w);
        }
        __syncthreads();

        #pragma unroll
        for (int ks = 0; ks < 2; ks++) {
            uint32_t af[2][4];
            ldsm4(af[0], aa + ks * 32);
            ldsm4(af[1], aa + 16 * 80 + ks * 32);
            #pragma unroll
            for (int ntp = 0; ntp < 4; ntp++) {
                uint32_t bf[4];
                ldsm4(bf, bb + ntp * (16 * 80) + ks * 32);
                #pragma unroll
                for (int mi = 0; mi < 2; mi++) {
                    mma_bf16(acc[mi][2 * ntp],     af[mi], bf[0], bf[1]);
                    mma_bf16(acc[mi][2 * ntp + 1], af[mi], bf[2], bf[3]);
                }
            }
        }
    }
    __syncthreads();

    // bias + stage to smem [256][72] bf16 (144B rows, 16B-aligned)
    {
        int r0 = lane >> 2, cp = 2 * (lane & 3);
        #pragma unroll
        for (int mi = 0; mi < 2; mi++) {
            int c = w * 32 + mi * 16 + r0;
            float bva = bv[c], bvb = bv[c + 8];
            #pragma unroll
            for (int nt = 0; nt < 8; nt++) {
                int n = nt * 8 + cp;
                STS32X(sb + PV_D + (uint32_t)c * 144 + n * 2,
                       cvt_bf16x2(acc[mi][nt][0] + bva, acc[mi][nt][1] + bva));
                STS32X(sb + PV_D + (uint32_t)(c + 8) * 144 + n * 2,
                       cvt_bf16x2(acc[mi][nt][2] + bvb, acc[mi][nt][3] + bvb));
            }
        }
    }
    __syncthreads();

    #pragma unroll
    for (int r = 0; r < 8; r++) {
        int fi = t + r * 256;
        int row = fi >> 3, c4 = fi & 7;
        uint4 v = *reinterpret_cast<const uint4*>(smv + PV_D + row * 144 + c4 * 16);
        *reinterpret_cast<uint4*>(
            g_V + (size_t)(b * NI + row) * NPIX + n0 + c4 * 8) = v;
    }
}

// ---------------------------------------------------------------------------
// HMMA flash attention. CTA = 128 q, 256 threads, cp.async double-buffered K/V.
// MMA1: fp16 single-pass k=32. MMA2: bf16 k=64.
// smem: sQ[128][40]h @0 (10240) | K0 @10240, K1 @15360 ([64][40]h, 5120)
//       V0 @20480, V1 @57344 ([256 c][64 j]bf16 stride 144, 36864)
//       sP @94208 ([128][64]bf16 stride 144, 18432) | lpart @112640 (1024)
// ---------------------------------------------------------------------------
#define OFF_Q  0
#define OFF_K0 10240
#define OFF_K1 15360
#define OFF_V0 20480
#define OFF_V1 57344
#define OFF_P  94208
#define OFF_L  112640
#define SMEM_BYTES (OFF_L + 1024)

__global__ __launch_bounds__(256, 1) void attn_kernel(
    const float* __restrict__ x, const float* __restrict__ gamma,
    float* __restrict__ out)
{
    extern __shared__ __align__(16) char smraw[];
    const uint32_t sb = smem_u32(smraw);

    const int tid = threadIdx.x;
    const int w = tid >> 5, lane = tid & 31;
    const int warp_m = w & 3, warp_n = w >> 2;
    const int b = blockIdx.y, n0 = blockIdx.x * BM;

    const int a_r = (lane & 7) + (lane & 8);
    const int a_k = (lane & 16) >> 1;
    const int b_r = (lane & 7) + ((lane & 16) >> 1);
    const int b_k = lane & 8;

    float* lpart = reinterpret_cast<float*>(smraw + OFF_L);

    // ---- Q tile [128][32] fp16 ----
    {
        const uint4* Qg = reinterpret_cast<const uint4*>(g_Q + (size_t)(b * NPIX + n0) * 32);
        #pragma unroll
        for (int r = 0; r < 2; r++) {
            int fi = tid + r * 256;
            int row = fi >> 2, c = fi & 3;
            uint4 v = Qg[fi];
            STS128X(sb + OFF_Q + row * 80 + c * 16, v.x, v.y, v.z, v.w);
        }
    }

    float oacc[2][16][4];
    #pragma unroll
    for (int mi = 0; mi < 2; mi++)
        #pragma unroll
        for (int nt = 0; nt < 16; nt++)
            #pragma unroll
            for (int k = 0; k < 4; k++) oacc[mi][nt][k] = 0.f;
    float lacc[2][2] = {{0.f, 0.f}, {0.f, 0.f}};

    const uint32_t qa_off = sb + OFF_Q + (uint32_t)(warp_m * 32 + a_r) * 80 + a_k * 2;
    const uint32_t kb_base[2] = {
        sb + OFF_K0 + (uint32_t)(warp_n * 32 + b_r) * 80 + b_k * 2,
        sb + OFF_K1 + (uint32_t)(warp_n * 32 + b_r) * 80 + b_k * 2 };
    const uint32_t vb_base[2] = {
        sb + OFF_V0 + (uint32_t)(warp_n * 128 + b_r) * 144 + b_k * 2,
        sb + OFF_V1 + (uint32_t)(warp_n * 128 + b_r) * 144 + b_k * 2 };
    const uint32_t pa_off = sb + OFF_P + (uint32_t)(warp_m * 32 + a_r) * 144 + a_k * 2;

    // prefetch tile 0
    {
        const char* Kg = reinterpret_cast<const char*>(g_K + (size_t)(b * NPIX) * 32);
        int row = tid >> 2, c = tid & 3;
        cp16(sb + OFF_K0 + row * 80 + c * 16, Kg + row * 64 + c * 16);
        #pragma unroll
        for (int r = 0; r < 8; r++) {
            int fi = tid + r * 256;
            int cc = fi >> 3, g = fi & 7;
            cp16(sb + OFF_V0 + cc * 144 + g * 16,
                 reinterpret_cast<const char*>(g_V + (size_t)(b * NI + cc) * NPIX) + g * 16);
        }
        CP_COMMIT();
    }

    #pragma unroll 1
    for (int jt = 0; jt < NT; jt++) {
        const int buf = jt & 1;
        CP_WAIT0();
        __syncthreads();

        if (jt + 1 < NT) {
            const int j1 = (jt + 1) * BN, nb = buf ^ 1;
            const char* Kg = reinterpret_cast<const char*>(g_K + (size_t)(b * NPIX + j1) * 32);
            int row = tid >> 2, c = tid & 3;
            cp16(sb + (nb ? OFF_K1 : OFF_K0) + row * 80 + c * 16, Kg + row * 64 + c * 16);
            #pragma unroll
            for (int r = 0; r < 8; r++) {
                int fi = tid + r * 256;
                int cc = fi >> 3, g = fi & 7;
                cp16(sb + (nb ? OFF_V1 : OFF_V0) + cc * 144 + g * 16,
                     reinterpret_cast<const char*>(
                         g_V + (size_t)(b * NI + cc) * NPIX + j1) + g * 16);
            }
            CP_COMMIT();
        }

        // ---- MMA1 (fp16): S(32q x 32j per warp), k=32 ----
        float sacc[2][4][4];
        #pragma unroll
        for (int mi = 0; mi < 2; mi++)
            #pragma unroll
            for (int ni = 0; ni < 4; ni++)
                #pragma unroll
                for (int k = 0; k < 4; k++) sacc[mi][ni][k] = 0.f;

        #pragma unroll
        for (int ks = 0; ks < 2; ks++) {
            uint32_t af[2][4], bf[2][4];
            ldsm4(af[0], qa_off + ks * 32);
            ldsm4(af[1], qa_off + 16 * 80 + ks * 32);
            ldsm4(bf[0], kb_base[buf] + ks * 32);
            ldsm4(bf[1], kb_base[buf] + 16 * 80 + ks * 32);
            #pragma unroll
            for (int mi = 0; mi < 2; mi++)
                #pragma unroll
                for (int ni = 0; ni < 4; ni++)
                    mma_fp16(sacc[mi][ni], af[mi], bf[ni >> 1][(ni & 1) * 2],
                             bf[ni >> 1][(ni & 1) * 2 + 1]);
        }

        // ---- exp + pack P (bf16) ----
        {
            const int q0 = warp_m * 32 + (lane >> 2);
            const int c0 = warp_n * 32 + 2 * (lane & 3);
            #pragma unroll
            for (int mi = 0; mi < 2; mi++) {
                uint32_t rowa = sb + OFF_P + (uint32_t)(q0 + mi * 16) * 144 + c0 * 2;
                #pragma unroll
                for (int ni = 0; ni < 4; ni++) {
                    float e0 = __expf(sacc[mi][ni][0]);
                    float e1 = __expf(sacc[mi][ni][1]);
                    float e2 = __expf(sacc[mi][ni][2]);
                    float e3 = __expf(sacc[mi][ni][3]);
                    lacc[mi][0] += e0 + e1;
                    lacc[mi][1] += e2 + e3;
                    STS32X(rowa + ni * 16, cvt_bf16x2(e0, e1));
                    STS32X(rowa + 8 * 144 + ni * 16, cvt_bf16x2(e2, e3));
                }
            }
        }
        __syncthreads();

        // ---- MMA2 (bf16): O += P @ V^T, k=64 ----
        #pragma unroll
        for (int ks = 0; ks < 4; ks++) {
            uint32_t af[2][4];
            ldsm4(af[0], pa_off + ks * 32);
            ldsm4(af[1], pa_off + 16 * 144 + ks * 32);
            #pragma unroll
            for (int ntp = 0; ntp < 8; ntp++) {
                uint32_t bf[4];
                ldsm4(bf, vb_base[buf] + ntp * (16 * 144) + ks * 32);
                #pragma unroll
                for (int mi = 0; mi < 2; mi++) {
                    mma_bf16(oacc[mi][2 * ntp],     af[mi], bf[0], bf[1]);
                    mma_bf16(oacc[mi][2 * ntp + 1], af[mi], bf[2], bf[3]);
                }
            }
        }
    }

    // ---- row-sum reduce ----
    #pragma unroll
    for (int mi = 0; mi < 2; mi++)
        #pragma unroll
        for (int rh = 0; rh < 2; rh++) {
            float v = lacc[mi][rh];
            v += __shfl_xor_sync(0xffffffffu, v, 1);
            v += __shfl_xor_sync(0xffffffffu, v, 2);
            lacc[mi][rh] = v;
        }
    __syncthreads();
    if ((lane & 3) == 0) {
        #pragma unroll
        for (int mi = 0; mi < 2; mi++)
            #pragma unroll
            for (int rh = 0; rh < 2; rh++)
                lpart[warp_n * 128 + warp_m * 32 + mi * 16 + (lane >> 2) + 8 * rh] =
                    lacc[mi][rh];
    }
    __syncthreads();

    float linv[2][2];
    #pragma unroll
    for (int mi = 0; mi < 2; mi++)
        #pragma unroll
        for (int rh = 0; rh < 2; rh++) {
            int row = warp_m * 32 + mi * 16 + (lane >> 2) + 8 * rh;
            linv[mi][rh] = 1.f / (lpart[row] + lpart[128 + row]);
        }

    // ---- epilogue ----
    #pragma unroll
    for (int mi = 0; mi < 2; mi++) {
        int q0 = n0 + warp_m * 32 + mi * 16 + (lane >> 2);
        #pragma unroll
        for (int nt = 0; nt < 16; nt++) {
            int c0 = warp_n * 128 + nt * 8 + 2 * (lane & 3);
            float ga = gamma[c0], gb = gamma[c0 + 1];
            size_t i00 = (size_t)(b * NI + c0) * NPIX + q0;
            out[i00]            = ga * oacc[mi][nt][0] * linv[mi][0] + x[i00];
            out[i00 + NPIX]     = gb * oacc[mi][nt][1] * linv[mi][0] + x[i00 + NPIX];
            out[i00 + 8]        = ga * oacc[mi][nt][2] * linv[mi][1] + x[i00 + 8];
            out[i00 + NPIX + 8] = gb * oacc[mi][nt][3] * linv[mi][1] + x[i00 + NPIX + 8];
        }
    }
}

// ---------------------------------------------------------------------------
extern "C" void kernel_launch(void* const* d_in, const int* in_sizes, int n_in,
                              void* d_out, int out_size)
{
    const float* x     = (const float*)d_in[0];
    const float* wq    = (const float*)d_in[1];
    const float* bq    = (const float*)d_in[2];
    const float* wk    = (const float*)d_in[3];
    const float* bk    = (const float*)d_in[4];
    const float* wv    = (const float*)d_in[5];
    const float* bv    = (const float*)d_in[6];
    const float* gamma = (const float*)d_in[7];
    float* out = (float*)d_out;

    cudaFuncSetAttribute(attn_kernel,
                         cudaFuncAttributeMaxDynamicSharedMemorySize, SMEM_BYTES);

    dim3 blk(256);
    conv_w_kernel<<<64, 256>>>(wv);
    proj_qk_kernel<<<dim3(32, 1, BS), blk>>>(x, wq, bq, wk, bk);
    proj_v_kernel<<<dim3(64, BS), blk>>>(x, bv);
    attn_kernel<<<dim3(NPIX / BM, BS), blk, SMEM_BYTES>>>(x, gamma, out);
}

// round 8
// speedup vs baseline: 7.5376x; 1.0606x over previous
#include <cuda_runtime.h>
#include <cuda_bf16.h>
#include <cuda_fp16.h>
#include <cstdint>

#define NI   256
#define QK   32
#define BS   4
#define NPIX 4096
#define BM   128
#define BN   64
#define NT   (NPIX / BN)

// ---------------- scratch (16B-aligned: vectorized access) ----------------
__device__ __align__(16) __half         g_Q[BS * NPIX * 32];    // [b][n][32] fp16
__device__ __align__(16) __half         g_K[BS * NPIX * 32];    // [b][n][32] fp16
__device__ __align__(16) __nv_bfloat16  g_V[BS * NI * NPIX];    // [b][c][n] bf16
__device__ __align__(16) __nv_bfloat16  g_Wv[NI * NI];          // V weights bf16

// ---------------- helpers ----------------
__device__ __forceinline__ uint32_t smem_u32(const void* p) {
    uint32_t a;
    asm("{ .reg .u64 t; cvta.to.shared.u64 t, %1; cvt.u32.u64 %0, t; }" : "=r"(a) : "l"(p));
    return a;
}
__device__ __forceinline__ uint32_t cvt_bf16x2(float lo, float hi) {
    uint32_t r;
    asm("cvt.rn.bf16x2.f32 %0, %1, %2;" : "=r"(r) : "f"(hi), "f"(lo));
    return r;
}
__device__ __forceinline__ void ldsm4(uint32_t* r, uint32_t addr) {
    asm volatile("ldmatrix.sync.aligned.m8n8.x4.shared.b16 {%0,%1,%2,%3}, [%4];"
        : "=r"(r[0]), "=r"(r[1]), "=r"(r[2]), "=r"(r[3]) : "r"(addr));
}
__device__ __forceinline__ void mma_bf16(float* d, const uint32_t* a,
                                         uint32_t b0, uint32_t b1) {
    asm volatile("mma.sync.aligned.m16n8k16.row.col.f32.bf16.bf16.f32 "
        "{%0,%1,%2,%3}, {%4,%5,%6,%7}, {%8,%9}, {%0,%1,%2,%3};"
        : "+f"(d[0]), "+f"(d[1]), "+f"(d[2]), "+f"(d[3])
        : "r"(a[0]), "r"(a[1]), "r"(a[2]), "r"(a[3]), "r"(b0), "r"(b1));
}
__device__ __forceinline__ void mma_fp16(float* d, const uint32_t* a,
                                         uint32_t b0, uint32_t b1) {
    asm volatile("mma.sync.aligned.m16n8k16.row.col.f32.f16.f16.f32 "
        "{%0,%1,%2,%3}, {%4,%5,%6,%7}, {%8,%9}, {%0,%1,%2,%3};"
        : "+f"(d[0]), "+f"(d[1]), "+f"(d[2]), "+f"(d[3])
        : "r"(a[0]), "r"(a[1]), "r"(a[2]), "r"(a[3]), "r"(b0), "r"(b1));
}
#define STS128X(a, r0, r1, r2, r3) \
    asm volatile("st.shared.v4.b32 [%0], {%1,%2,%3,%4};" :: "r"(a), "r"(r0), "r"(r1), "r"(r2), "r"(r3) : "memory")
#define STS32X(a, r0) \
    asm volatile("st.shared.b32 [%0], %1;" :: "r"(a), "r"(r0) : "memory")
__device__ __forceinline__ void cp16(uint32_t dst, const void* src) {
    asm volatile("cp.async.cg.shared.global [%0], [%1], 16;" :: "r"(dst), "l"(src) : "memory");
}
#define CP_COMMIT() asm volatile("cp.async.commit_group;" ::: "memory")
#define CP_WAIT0()  asm volatile("cp.async.wait_group 0;" ::: "memory")

// ---------------------------------------------------------------------------
// W_v -> bf16 convert (one-time tiny kernel)
// ---------------------------------------------------------------------------
__global__ void conv_w_kernel(const float* __restrict__ W) {
    int i = blockIdx.x * 256 + threadIdx.x;          // 16384 float4s
    float4 v = reinterpret_cast<const float4*>(W)[i];
    uint2 o;
    o.x = cvt_bf16x2(v.x, v.y);
    o.y = cvt_bf16x2(v.z, v.w);
    reinterpret_cast<uint2*>(g_Wv)[i] = o;
}

// ---------------------------------------------------------------------------
// Fused Q+K projection (exact fp32 FFMA), output fp16 [b][n][32]
// ---------------------------------------------------------------------------
__global__ __launch_bounds__(256) void proj_qk_kernel(
    const float* __restrict__ x,
    const float* __restrict__ Wq, const float* __restrict__ bq,
    const float* __restrict__ Wk, const float* __restrict__ bk)
{
    __shared__ float sX[4352];
    __shared__ float sWq[32 * 33];
    __shared__ float sWk[32 * 33];
    __shared__ __align__(16) __half sObq[128 * 40];
    __shared__ __align__(16) __half sObk[128 * 40];

    const int t = threadIdx.x, nx = t & 31, oy = t >> 5;
    const int b = blockIdx.z, n0 = blockIdx.x * 128;

    float aq[4][4], ak[4][4];
    #pragma unroll
    for (int i = 0; i < 4; i++)
        #pragma unroll
        for (int j = 0; j < 4; j++) { aq[i][j] = 0.f; ak[i][j] = 0.f; }

    for (int k0 = 0; k0 < NI; k0 += 32) {
        const float4* xp = reinterpret_cast<const float4*>(
            x + ((size_t)(b * NI + k0)) * NPIX + n0);
        #pragma unroll
        for (int r = 0; r < 4; r++) {
            int fi = t + r * 256;
            reinterpret_cast<float4*>(sX)[(fi >> 5) * 32 + (fi & 31)] =
                xp[(size_t)(fi >> 5) * 1024 + (fi & 31)];
        }
        #pragma unroll
        for (int r = 0; r < 4; r++) {
            int ei = t + r * 256;
            sWq[(ei >> 5) * 33 + (ei & 31)] = Wq[(size_t)(ei >> 5) * NI + k0 + (ei & 31)];
            sWk[(ei >> 5) * 33 + (ei & 31)] = Wk[(size_t)(ei >> 5) * NI + k0 + (ei & 31)];
        }
        __syncthreads();
        #pragma unroll
        for (int kk = 0; kk < 32; kk++) {
            float wq[4], wk[4], xf[4];
            #pragma unroll
            for (int i = 0; i < 4; i++) {
                wq[i] = sWq[(oy + 8 * i) * 33 + kk];
                wk[i] = sWk[(oy + 8 * i) * 33 + kk];
            }
            #pragma unroll
            for (int j = 0; j < 4; j++) xf[j] = sX[kk * 128 + nx + 32 * j];
            #pragma unroll
            for (int i = 0; i < 4; i++)
                #pragma unroll
                for (int j = 0; j < 4; j++) {
                    aq[i][j] = fmaf(wq[i], xf[j], aq[i][j]);
                    ak[i][j] = fmaf(wk[i], xf[j], ak[i][j]);
                }
        }
        __syncthreads();
    }

    #pragma unroll
    for (int i = 0; i < 4; i++) {
        int o = oy + 8 * i;
        float bbq = bq[o], bbk = bk[o];
        #pragma unroll
        for (int j = 0; j < 4; j++) {
            int n = nx + 32 * j;
            sObq[n * 40 + o] = __float2half_rn(aq[i][j] + bbq);
            sObk[n * 40 + o] = __float2half_rn(ak[i][j] + bbk);
        }
    }
    __syncthreads();

    uint4* dq = reinterpret_cast<uint4*>(g_Q + (size_t)(b * NPIX + n0) * 32);
    uint4* dk = reinterpret_cast<uint4*>(g_K + (size_t)(b * NPIX + n0) * 32);
    #pragma unroll
    for (int r = 0; r < 2; r++) {
        int fi = t + r * 256;
        int row = fi >> 2, c = fi & 3;
        dq[fi] = *reinterpret_cast<const uint4*>(sObq + row * 40 + c * 8);
        dk[fi] = *reinterpret_cast<const uint4*>(sObk + row * 40 + c * 8);
    }
}

// ---------------------------------------------------------------------------
// V projection via bf16 HMMA: V[c][n] = sum_k Wv[c][k] x[k][n] + bv[c]
// ---------------------------------------------------------------------------
#define PV_A 0
#define PV_B 20480
#define PV_D 0
#define PV_SMEM 36864

__global__ __launch_bounds__(256) void proj_v_kernel(
    const float* __restrict__ x, const float* __restrict__ bv)
{
    __shared__ __align__(16) char smv[PV_SMEM];
    const uint32_t sb = smem_u32(smv);

    const int t = threadIdx.x, w = t >> 5, lane = t & 31;
    const int b = blockIdx.y, n0 = blockIdx.x * 64;

    const int a_r = (lane & 7) + (lane & 8);
    const int a_k = (lane & 16) >> 1;
    const int b_r = (lane & 7) + ((lane & 16) >> 1);
    const int b_k = lane & 8;

    float acc[2][8][4];
    #pragma unroll
    for (int mi = 0; mi < 2; mi++)
        #pragma unroll
        for (int nt = 0; nt < 8; nt++)
            #pragma unroll
            for (int k = 0; k < 4; k++) acc[mi][nt][k] = 0.f;

    const uint32_t aa = sb + PV_A + (uint32_t)(w * 32 + a_r) * 80 + a_k * 2;
    const uint32_t bb = sb + PV_B + (uint32_t)b_r * 80 + b_k * 2;

    for (int kc = 0; kc < NI; kc += 32) {
        if (kc) __syncthreads();
        #pragma unroll
        for (int r = 0; r < 4; r++) {
            int fi = t + r * 256;
            int row = fi >> 2, c = fi & 3;
            uint4 v = *reinterpret_cast<const uint4*>(g_Wv + row * NI + kc + c * 8);
            STS128X(sb + PV_A + row * 80 + c * 16, v.x, v.y, v.z, v.w);
        }
        #pragma unroll
        for (int r = 0; r < 2; r++) {
            int fi = t + r * 256;
            int kk = fi >> 4, f4 = fi & 15;
            float4 xv = *reinterpret_cast<const float4*>(
                x + (size_t)(b * NI + kc + kk) * NPIX + n0 + f4 * 4);
            __nv_bfloat16* bp = reinterpret_cast<__nv_bfloat16*>(smv + PV_B);
            bp[(f4 * 4 + 0) * 40 + kk] = __float2bfloat16(xv.x);
            bp[(f4 * 4 + 1) * 40 + kk] = __float2bfloat16(xv.y);
            bp[(f4 * 4 + 2) * 40 + kk] = __float2bfloat16(xv.z);
            bp[(f4 * 4 + 3) * 40 + kk] = __float2bfloat16(xv.w);
        }
        __syncthreads();

        #pragma unroll
        for (int ks = 0; ks < 2; ks++) {
            uint32_t af[2][4];
            ldsm4(af[0], aa + ks * 32);
            ldsm4(af[1], aa + 16 * 80 + ks * 32);
            #pragma unroll
            for (int ntp = 0; ntp < 4; ntp++) {
                uint32_t bf[4];
                ldsm4(bf, bb + ntp * (16 * 80) + ks * 32);
                #pragma unroll
                for (int mi = 0; mi < 2; mi++) {
                    mma_bf16(acc[mi][2 * ntp],     af[mi], bf[0], bf[1]);
                    mma_bf16(acc[mi][2 * ntp + 1], af[mi], bf[2], bf[3]);
                }
            }
        }
    }
    __syncthreads();

    {
        int r0 = lane >> 2, cp = 2 * (lane & 3);
        #pragma unroll
        for (int mi = 0; mi < 2; mi++) {
            int c = w * 32 + mi * 16 + r0;
            float bva = bv[c], bvb = bv[c + 8];
            #pragma unroll
            for (int nt = 0; nt < 8; nt++) {
                int n = nt * 8 + cp;
                STS32X(sb + PV_D + (uint32_t)c * 144 + n * 2,
                       cvt_bf16x2(acc[mi][nt][0] + bva, acc[mi][nt][1] + bva));
                STS32X(sb + PV_D + (uint32_t)(c + 8) * 144 + n * 2,
                       cvt_bf16x2(acc[mi][nt][2] + bvb, acc[mi][nt][3] + bvb));
            }
        }
    }
    __syncthreads();

    #pragma unroll
    for (int r = 0; r < 8; r++) {
        int fi = t + r * 256;
        int row = fi >> 3, c4 = fi & 7;
        uint4 v = *reinterpret_cast<const uint4*>(smv + PV_D + row * 144 + c4 * 16);
        *reinterpret_cast<uint4*>(
            g_V + (size_t)(b * NI + row) * NPIX + n0 + c4 * 8) = v;
    }
}

// ---------------------------------------------------------------------------
// HMMA flash attention, register-resident P.
// 8 warps; warp w owns q rows [w*16, w*16+16). Each warp: full S row band
// (16q x 64j), exp in registers, P = A-fragments packed from S accumulators
// (C-frag layout == A-frag layout), MMA2 over all 256 channels.
// smem: sQ[128][40]h @0 | K0 @10240, K1 @15360 ([64][40]h)
//       V0 @20480, V1 @57344 ([256 c][72 j]bf16 stride 144)
// ---------------------------------------------------------------------------
#define OFF_Q  0
#define OFF_K0 10240
#define OFF_K1 15360
#define OFF_V0 20480
#define OFF_V1 57344
#define SMEM_BYTES 94208

__global__ __launch_bounds__(256, 1) void attn_kernel(
    const float* __restrict__ x, const float* __restrict__ gamma,
    float* __restrict__ out)
{
    extern __shared__ __align__(16) char smraw[];
    const uint32_t sb = smem_u32(smraw);

    const int tid = threadIdx.x;
    const int w = tid >> 5, lane = tid & 31;
    const int b = blockIdx.y, n0 = blockIdx.x * BM;

    const int a_r = (lane & 7) + (lane & 8);
    const int a_k = (lane & 16) >> 1;
    const int b_r = (lane & 7) + ((lane & 16) >> 1);
    const int b_k = lane & 8;

    // ---- Q tile [128][32] fp16 ----
    {
        const uint4* Qg = reinterpret_cast<const uint4*>(g_Q + (size_t)(b * NPIX + n0) * 32);
        #pragma unroll
        for (int r = 0; r < 2; r++) {
            int fi = tid + r * 256;
            int row = fi >> 2, c = fi & 3;
            uint4 v = Qg[fi];
            STS128X(sb + OFF_Q + row * 80 + c * 16, v.x, v.y, v.z, v.w);
        }
    }

    // prefetch tile 0 (K + V)
    {
        const char* Kg = reinterpret_cast<const char*>(g_K + (size_t)(b * NPIX) * 32);
        int row = tid >> 2, c = tid & 3;
        cp16(sb + OFF_K0 + row * 80 + c * 16, Kg + row * 64 + c * 16);
        #pragma unroll
        for (int r = 0; r < 8; r++) {
            int fi = tid + r * 256;
            int cc = fi >> 3, g = fi & 7;
            cp16(sb + OFF_V0 + cc * 144 + g * 16,
                 reinterpret_cast<const char*>(g_V + (size_t)(b * NI + cc) * NPIX) + g * 16);
        }
        CP_COMMIT();
    }
    __syncthreads();

    // Q A-fragments: loaded once (invariant over key tiles)
    uint32_t af[2][4];
    {
        const uint32_t qa_off = sb + OFF_Q + (uint32_t)(w * 16 + a_r) * 80 + a_k * 2;
        ldsm4(af[0], qa_off);
        ldsm4(af[1], qa_off + 32);
    }

    const uint32_t kb_base[2] = {
        sb + OFF_K0 + (uint32_t)b_r * 80 + b_k * 2,
        sb + OFF_K1 + (uint32_t)b_r * 80 + b_k * 2 };
    const uint32_t vb_base[2] = {
        sb + OFF_V0 + (uint32_t)b_r * 144 + b_k * 2,
        sb + OFF_V1 + (uint32_t)b_r * 144 + b_k * 2 };

    float oacc[32][4];
    #pragma unroll
    for (int ct = 0; ct < 32; ct++)
        #pragma unroll
        for (int k = 0; k < 4; k++) oacc[ct][k] = 0.f;
    float lacc[2] = {0.f, 0.f};

    #pragma unroll 1
    for (int jt = 0; jt < NT; jt++) {
        const int buf = jt & 1;
        CP_WAIT0();
        __syncthreads();

        if (jt + 1 < NT) {
            const int j1 = (jt + 1) * BN, nb = buf ^ 1;
            const char* Kg = reinterpret_cast<const char*>(g_K + (size_t)(b * NPIX + j1) * 32);
            int row = tid >> 2, c = tid & 3;
            cp16(sb + (nb ? OFF_K1 : OFF_K0) + row * 80 + c * 16, Kg + row * 64 + c * 16);
            #pragma unroll
            for (int r = 0; r < 8; r++) {
                int fi = tid + r * 256;
                int cc = fi >> 3, g = fi & 7;
                cp16(sb + (nb ? OFF_V1 : OFF_V0) + cc * 144 + g * 16,
                     reinterpret_cast<const char*>(
                         g_V + (size_t)(b * NI + cc) * NPIX + j1) + g * 16);
            }
            CP_COMMIT();
        }

        // ---- MMA1 (fp16): S = Q K^T, per-warp 16q x 64j, k=32 ----
        float sacc[8][4];
        #pragma unroll
        for (int ni = 0; ni < 8; ni++)
            #pragma unroll
            for (int k = 0; k < 4; k++) sacc[ni][k] = 0.f;

        #pragma unroll
        for (int ks = 0; ks < 2; ks++) {
            uint32_t bfn[4][4];
            #pragma unroll
            for (int np = 0; np < 4; np++)
                ldsm4(bfn[np], kb_base[buf] + np * (16 * 80) + ks * 32);
            #pragma unroll
            for (int ni = 0; ni < 8; ni++)
                mma_fp16(sacc[ni], af[ks], bfn[ni >> 1][(ni & 1) * 2],
                         bfn[ni >> 1][(ni & 1) * 2 + 1]);
        }

        // ---- exp in registers + row sums ----
        #pragma unroll
        for (int ni = 0; ni < 8; ni++) {
            float e0 = __expf(sacc[ni][0]);
            float e1 = __expf(sacc[ni][1]);
            float e2 = __expf(sacc[ni][2]);
            float e3 = __expf(sacc[ni][3]);
            lacc[0] += e0 + e1;
            lacc[1] += e2 + e3;
            sacc[ni][0] = e0; sacc[ni][1] = e1;
            sacc[ni][2] = e2; sacc[ni][3] = e3;
        }

        // ---- MMA2 (bf16): O += P @ V^T; P packed from S accumulators ----
        #pragma unroll
        for (int ks2 = 0; ks2 < 4; ks2++) {
            uint32_t pa[4];
            pa[0] = cvt_bf16x2(sacc[2 * ks2][0],     sacc[2 * ks2][1]);
            pa[1] = cvt_bf16x2(sacc[2 * ks2][2],     sacc[2 * ks2][3]);
            pa[2] = cvt_bf16x2(sacc[2 * ks2 + 1][0], sacc[2 * ks2 + 1][1]);
            pa[3] = cvt_bf16x2(sacc[2 * ks2 + 1][2], sacc[2 * ks2 + 1][3]);
            #pragma unroll
            for (int ntp = 0; ntp < 16; ntp++) {
                uint32_t bf[4];
                ldsm4(bf, vb_base[buf] + ntp * (16 * 144) + ks2 * 32);
                mma_bf16(oacc[2 * ntp],     pa, bf[0], bf[1]);
                mma_bf16(oacc[2 * ntp + 1], pa, bf[2], bf[3]);
            }
        }
    }

    // ---- row-sum reduce (intra-quad) ----
    #pragma unroll
    for (int rh = 0; rh < 2; rh++) {
        float v = lacc[rh];
        v += __shfl_xor_sync(0xffffffffu, v, 1);
        v += __shfl_xor_sync(0xffffffffu, v, 2);
        lacc[rh] = 1.f / v;
    }

    // ---- epilogue: out = gamma*O/l + x ----
    {
        int q0 = n0 + w * 16 + (lane >> 2);
        #pragma unroll
        for (int ct = 0; ct < 32; ct++) {
            int c0 = ct * 8 + 2 * (lane & 3);
            float ga = gamma[c0], gb = gamma[c0 + 1];
            size_t i00 = (size_t)(b * NI + c0) * NPIX + q0;
            out[i00]            = ga * oacc[ct][0] * lacc[0] + x[i00];
            out[i00 + NPIX]     = gb * oacc[ct][1] * lacc[0] + x[i00 + NPIX];
            out[i00 + 8]        = ga * oacc[ct][2] * lacc[1] + x[i00 + 8];
            out[i00 + NPIX + 8] = gb * oacc[ct][3] * lacc[1] + x[i00 + NPIX + 8];
        }
    }
}

// ---------------------------------------------------------------------------
extern "C" void kernel_launch(void* const* d_in, const int* in_sizes, int n_in,
                              void* d_out, int out_size)
{
    const float* x     = (const float*)d_in[0];
    const float* wq    = (const float*)d_in[1];
    const float* bq    = (const float*)d_in[2];
    const float* wk    = (const float*)d_in[3];
    const float* bk    = (const float*)d_in[4];
    const float* wv    = (const float*)d_in[5];
    const float* bv    = (const float*)d_in[6];
    const float* gamma = (const float*)d_in[7];
    float* out = (float*)d_out;

    cudaFuncSetAttribute(attn_kernel,
                         cudaFuncAttributeMaxDynamicSharedMemorySize, SMEM_BYTES);

    dim3 blk(256);
    conv_w_kernel<<<64, 256>>>(wv);
    proj_qk_kernel<<<dim3(32, 1, BS), blk>>>(x, wq, bq, wk, bk);
    proj_v_kernel<<<dim3(64, BS), blk>>>(x, bv);
    attn_kernel<<<dim3(NPIX / BM, BS), blk, SMEM_BYTES>>>(x, gamma, out);
}